// round 7
// baseline (speedup 1.0000x reference)
#include <cuda_runtime.h>
#include <cuda_bf16.h>
#include <math.h>

// ---------------- problem constants ----------------
#define B_    32
#define S_    512
#define H_    768
#define W_    128
#define G_    4
#define NH_   4
#define HD_   192
#define FF_   2048
#define NL_   2
#define NLAB_ 6
#define LW    129           // W + 1
#define MT    (B_ * LW)     // 4128 total rows
#define EPS_  1e-5f

// ---------------- scratch (no cudaMalloc allowed) ----------------
__device__ float g_x  [(size_t)MT * H_];        // residual stream (B*Lw, 768)
__device__ float g_qkv[(size_t)MT * 3 * H_];    // (B*Lw, 2304)
__device__ float g_tmp[(size_t)MT * FF_];       // widest temp (B*Lw, 2048)
__device__ float g_ctx[(size_t)MT * H_];        // attention ctx / ff2 out
__device__ float g_gm [(size_t)B_ * W_ * G_];   // normalized group mask (0/1)
__device__ float g_wv [(size_t)B_ * W_];        // normalized word_valid (0/1)

// ---------------- mask dtype auto-detect + normalize ----------------
// Masks are numpy bools in the reference; the harness may pass them as
// int32, uint8, or float32. Detect by scanning raw uint32 words:
//   max == 1           -> int32 0/1
//   max >= 0x3F000000  -> float32 (1.0f = 0x3F800000)
//   else               -> uint8 byte-packed (e.g. 0x01010101)
// word_valid is guaranteed to contain runs of ones (nwords >= W/2) and
// every group has glen >= 1, so max >= 1 always -> unambiguous.
__device__ __forceinline__ int classify_mode(unsigned int mx) {
    if (mx <= 1u) return 0;            // int32
    if (mx >= 0x3F000000u) return 2;   // float32
    return 1;                          // uint8
}
__device__ __forceinline__ float decode_mask(const void* p, int i, int mode) {
    if (mode == 0) return (float)((const int*)p)[i];
    if (mode == 1) return (float)((const unsigned char*)p)[i];
    return ((const float*)p)[i];
}

__global__ void norm_mask_kernel(const void* __restrict__ gm_raw,
                                 const void* __restrict__ wv_raw,
                                 float* __restrict__ gm,
                                 float* __restrict__ wv)
{
    __shared__ unsigned int smx[2];
    __shared__ unsigned int red[8];
    int tid = threadIdx.x, lane = tid & 31, w = tid >> 5;

    // detect: scan the minimum-safe number of 4-byte words
    // gmask: 16384 elems -> >= 16384 bytes -> 4096 words safe
    // wvalid: 4096 elems -> >= 4096 bytes -> 1024 words safe
    for (int which = 0; which < 2; which++) {
        const unsigned int* p = (const unsigned int*)(which ? wv_raw : gm_raw);
        int nw = which ? 1024 : 4096;
        unsigned int mx = 0;
        for (int i = tid; i < nw; i += 256) mx = max(mx, p[i]);
#pragma unroll
        for (int o = 16; o > 0; o >>= 1)
            mx = max(mx, __shfl_xor_sync(0xffffffffu, mx, o));
        if (lane == 0) red[w] = mx;
        __syncthreads();
        if (tid == 0) {
            unsigned int m = 0;
#pragma unroll
            for (int i = 0; i < 8; i++) m = max(m, red[i]);
            smx[which] = m;
        }
        __syncthreads();
    }
    int mode_g = classify_mode(smx[0]);
    int mode_w = classify_mode(smx[1]);

    for (int i = tid; i < B_ * W_ * G_; i += 256)
        gm[i] = decode_mask(gm_raw, i, mode_g);
    for (int i = tid; i < B_ * W_; i += 256)
        wv[i] = decode_mask(wv_raw, i, mode_w);
}

// ---------------- build x = [cls ; wordemb] ----------------
__global__ void build_x_kernel(const float* __restrict__ hidden,
                               const int*   __restrict__ idx,
                               const float* __restrict__ gmask,
                               const float* __restrict__ wvalid,
                               float* __restrict__ x)
{
    int row = blockIdx.x;            // 0..MT-1
    int b = row / LW, r = row % LW;
    const float* hb = hidden + (size_t)b * S_ * H_;
    float* xr = x + (size_t)row * H_;
    int tid = threadIdx.x;

    if (r == 0) {
        for (int c = tid; c < H_; c += blockDim.x) xr[c] = hb[c];
        return;
    }
    int w = r - 1;
    bool valid = wvalid[b * W_ + w] > 0.5f;
    const int*   ig = idx   + ((size_t)(b * W_ + w)) * G_;
    const float* mg = gmask + ((size_t)(b * W_ + w)) * G_;

    int   t[G_];
    bool  use[G_];
    float cnt = 0.f;
#pragma unroll
    for (int g = 0; g < G_; g++) {
        use[g] = mg[g] > 0.5f;
        t[g]   = ig[g];
        cnt   += use[g] ? 1.f : 0.f;
    }
    float inv = valid ? (1.f / fmaxf(cnt, 1.f)) : 0.f;
    for (int c = tid; c < H_; c += blockDim.x) {
        float s = 0.f;
#pragma unroll
        for (int g = 0; g < G_; g++)
            if (use[g]) s += hb[(size_t)t[g] * H_ + c];
        xr[c] = s * inv;
    }
}

// ---------------- GEMM: C[M,N] = A[M,K] @ Wt[N,K]^T + bias (opt relu) ----------------
// 64x64 tile, BK=16, 256 threads, 4x4 register block.
template <bool RELU>
__global__ void __launch_bounds__(256)
gemm_nt_kernel(const float* __restrict__ A, const float* __restrict__ Wt,
               const float* __restrict__ bias, float* __restrict__ C,
               int M, int N, int K)
{
    __shared__ float sA[16][65];
    __shared__ float sB[16][65];

    int tid = threadIdx.x;
    int tx = tid & 15;        // 0..15 (n-dim quad)
    int ty = tid >> 4;        // 0..15 (m-dim quad)
    int m0 = blockIdx.y * 64;
    int n0 = blockIdx.x * 64;

    float acc[4][4];
#pragma unroll
    for (int i = 0; i < 4; i++)
#pragma unroll
        for (int j = 0; j < 4; j++) acc[i][j] = 0.f;

    for (int k0 = 0; k0 < K; k0 += 16) {
        // load A tile (64 rows x 16 k), k along tx -> coalesced
#pragma unroll
        for (int r = 0; r < 4; r++) {
            int row = ty + r * 16;
            int m = m0 + row;
            sA[tx][row] = (m < M) ? A[(size_t)m * K + k0 + tx] : 0.f;
        }
#pragma unroll
        for (int r = 0; r < 4; r++) {
            int row = ty + r * 16;
            sB[tx][row] = Wt[(size_t)(n0 + row) * K + k0 + tx];
        }
        __syncthreads();
#pragma unroll
        for (int k = 0; k < 16; k++) {
            float a[4], bb[4];
#pragma unroll
            for (int i = 0; i < 4; i++) a[i]  = sA[k][ty * 4 + i];
#pragma unroll
            for (int j = 0; j < 4; j++) bb[j] = sB[k][tx * 4 + j];
#pragma unroll
            for (int i = 0; i < 4; i++)
#pragma unroll
                for (int j = 0; j < 4; j++) acc[i][j] += a[i] * bb[j];
        }
        __syncthreads();
    }

#pragma unroll
    for (int i = 0; i < 4; i++) {
        int m = m0 + ty * 4 + i;
        if (m >= M) continue;
#pragma unroll
        for (int j = 0; j < 4; j++) {
            int n = n0 + tx * 4 + j;
            float v = acc[i][j] + bias[n];
            if (RELU) v = fmaxf(v, 0.f);
            C[(size_t)m * N + n] = v;
        }
    }
}

// ---------------- attention: one block per (b, head) ----------------
// smem: K tile (129*192) + V tile (129*192) + q rows (8*192) + score rows (8*132)
#define ATTN_SMEM_FLOATS (2 * LW * HD_ + 8 * HD_ + 8 * 132)
__global__ void __launch_bounds__(256)
attn_kernel(const float* __restrict__ qkv,
            const float* __restrict__ wvalid,
            float* __restrict__ ctx)
{
    extern __shared__ float sm[];
    float* sK = sm;                          // [129][192]
    float* sV = sK + LW * HD_;               // [129][192]
    float* sQ = sV + LW * HD_;               // [8][192]
    float* sS = sQ + 8 * HD_;                // [8][132]
    __shared__ float sMask[LW];

    int bh = blockIdx.x;
    int b = bh / NH_, h = bh % NH_;
    int tid = threadIdx.x;
    const float* base = qkv + (size_t)b * LW * (3 * H_);
    const float scale = rsqrtf((float)HD_);

    for (int i = tid; i < LW * HD_; i += 256) {
        int t = i / HD_, d = i - t * HD_;
        size_t off = (size_t)t * (3 * H_) + h * HD_ + d;
        sK[i] = base[off + H_];
        sV[i] = base[off + 2 * H_];
    }
    if (tid < LW)
        sMask[tid] = (tid == 0 || wvalid[b * W_ + tid - 1] > 0.5f) ? 0.f : -1e30f;
    __syncthreads();

    int warp = tid >> 5, lane = tid & 31;
    float* srow = sS + warp * 132;
    float* sq   = sQ + warp * HD_;

    for (int q = warp; q < LW; q += 8) {
        const float* qv = base + (size_t)q * (3 * H_) + h * HD_;
        for (int d = lane; d < HD_; d += 32) sq[d] = qv[d];
        __syncwarp();

        // scores
        const float4* sq4 = (const float4*)sq;
        for (int k = lane; k < LW; k += 32) {
            const float4* kv4 = (const float4*)(sK + k * HD_);
            float s = 0.f;
#pragma unroll 8
            for (int d4 = 0; d4 < HD_ / 4; d4++) {
                float4 a = sq4[d4], c = kv4[d4];
                s += a.x * c.x + a.y * c.y + a.z * c.z + a.w * c.w;
            }
            srow[k] = s * scale + sMask[k];
        }
        __syncwarp();

        // softmax over 129
        float mx = -1e30f;
        for (int k = lane; k < LW; k += 32) mx = fmaxf(mx, srow[k]);
#pragma unroll
        for (int o = 16; o > 0; o >>= 1) mx = fmaxf(mx, __shfl_xor_sync(0xffffffffu, mx, o));
        float sum = 0.f;
        for (int k = lane; k < LW; k += 32) {
            float e = __expf(srow[k] - mx);
            srow[k] = e;
            sum += e;
        }
#pragma unroll
        for (int o = 16; o > 0; o >>= 1) sum += __shfl_xor_sync(0xffffffffu, sum, o);
        float inv = 1.f / sum;
        __syncwarp();

        // ctx = a @ V
        float* out = ctx + (size_t)(b * LW + q) * H_ + h * HD_;
        for (int d = lane; d < HD_; d += 32) {
            float acc = 0.f;
#pragma unroll 4
            for (int k = 0; k < LW; k++) acc += srow[k] * sV[k * HD_ + d];
            out[d] = acc * inv;
        }
        __syncwarp();
    }
}

// ---------------- fused residual-add + layernorm (in-place into x) ----------------
__global__ void __launch_bounds__(256)
add_ln_kernel(float* __restrict__ x, const float* __restrict__ y,
              const float* __restrict__ s, const float* __restrict__ bb)
{
    __shared__ float red[32];
    int row = blockIdx.x, tid = threadIdx.x;
    float* xr = x + (size_t)row * H_;
    const float* yr = y + (size_t)row * H_;

    float h[3];
    float sum = 0.f;
#pragma unroll
    for (int i = 0; i < 3; i++) {
        int c = tid + i * 256;
        h[i] = xr[c] + yr[c];
        sum += h[i];
    }
    // block reduce sum
    int lane = tid & 31, w = tid >> 5;
#pragma unroll
    for (int o = 16; o > 0; o >>= 1) sum += __shfl_xor_sync(0xffffffffu, sum, o);
    if (lane == 0) red[w] = sum;
    __syncthreads();
    if (w == 0) {
        float v = (lane < 8) ? red[lane] : 0.f;
#pragma unroll
        for (int o = 4; o > 0; o >>= 1) v += __shfl_xor_sync(0xffu, v, o);
        if (lane == 0) red[0] = v;
    }
    __syncthreads();
    float mean = red[0] * (1.f / H_);
    __syncthreads();

    float vs = 0.f;
#pragma unroll
    for (int i = 0; i < 3; i++) {
        float d = h[i] - mean;
        vs += d * d;
    }
#pragma unroll
    for (int o = 16; o > 0; o >>= 1) vs += __shfl_xor_sync(0xffffffffu, vs, o);
    if (lane == 0) red[w] = vs;
    __syncthreads();
    if (w == 0) {
        float v = (lane < 8) ? red[lane] : 0.f;
#pragma unroll
        for (int o = 4; o > 0; o >>= 1) v += __shfl_xor_sync(0xffu, v, o);
        if (lane == 0) red[0] = v;
    }
    __syncthreads();
    float var = red[0] * (1.f / H_);
    float rstd = rsqrtf(var + EPS_);

#pragma unroll
    for (int i = 0; i < 3; i++) {
        int c = tid + i * 256;
        xr[c] = (h[i] - mean) * rstd * s[c] + bb[c];
    }
}

// ---------------- classifier head + pooled copy ----------------
__global__ void __launch_bounds__(256)
cls_kernel(const float* __restrict__ x, const float* __restrict__ cw,
           const float* __restrict__ cb, float* __restrict__ out)
{
    int b = blockIdx.x, tid = threadIdx.x;
    const float* p = x + (size_t)b * LW * H_;   // row 0 of batch b = cls/pooled
    float* pooled = out + NLAB_ * B_ + (size_t)b * H_;
    for (int c = tid; c < H_; c += 256) pooled[c] = p[c];

    int warp = tid >> 5, lane = tid & 31;
    if (warp < NLAB_) {
        float s = 0.f;
        for (int c = lane; c < H_; c += 32) s += p[c] * cw[(size_t)warp * H_ + c];
#pragma unroll
        for (int o = 16; o > 0; o >>= 1) s += __shfl_xor_sync(0xffffffffu, s, o);
        if (lane == 0) out[b * NLAB_ + warp] = s + cb[warp];
    }
}

// ---------------- launcher ----------------
extern "C" void kernel_launch(void* const* d_in, const int* in_sizes, int n_in,
                              void* d_out, int out_size)
{
    const float* hidden = (const float*)d_in[0];
    const int*   widx   = (const int*)d_in[1];
    const void*  gmask  = (const void*)d_in[2];
    const void*  wvalid = (const void*)d_in[3];
    const float* qkv_w = (const float*)d_in[4];
    const float* qkv_b = (const float*)d_in[5];
    const float* out_w = (const float*)d_in[6];
    const float* out_b = (const float*)d_in[7];
    const float* ff1_w = (const float*)d_in[8];
    const float* ff1_b = (const float*)d_in[9];
    const float* ff2_w = (const float*)d_in[10];
    const float* ff2_b = (const float*)d_in[11];
    const float* ln1_s = (const float*)d_in[12];
    const float* ln1_b = (const float*)d_in[13];
    const float* ln2_s = (const float*)d_in[14];
    const float* ln2_b = (const float*)d_in[15];
    const float* cls_w = (const float*)d_in[16];
    const float* cls_b = (const float*)d_in[17];
    float* out = (float*)d_out;

    float *px, *pqkv, *ptmp, *pctx, *pgm, *pwv;
    cudaGetSymbolAddress((void**)&px,   g_x);
    cudaGetSymbolAddress((void**)&pqkv, g_qkv);
    cudaGetSymbolAddress((void**)&ptmp, g_tmp);
    cudaGetSymbolAddress((void**)&pctx, g_ctx);
    cudaGetSymbolAddress((void**)&pgm,  g_gm);
    cudaGetSymbolAddress((void**)&pwv,  g_wv);

    const int attn_smem = ATTN_SMEM_FLOATS * (int)sizeof(float);
    cudaFuncSetAttribute(attn_kernel, cudaFuncAttributeMaxDynamicSharedMemorySize, attn_smem);

    norm_mask_kernel<<<1, 256>>>(gmask, wvalid, pgm, pwv);
    build_x_kernel<<<MT, 256>>>(hidden, widx, pgm, pwv, px);

    for (int l = 0; l < NL_; l++) {
        // qkv = x @ qkv_w^T + b     (M=4128, N=2304, K=768)
        {
            dim3 grid(3 * H_ / 64, (MT + 63) / 64);
            gemm_nt_kernel<false><<<grid, 256>>>(px, qkv_w + (size_t)l * 3 * H_ * H_,
                                                 qkv_b + (size_t)l * 3 * H_, pqkv,
                                                 MT, 3 * H_, H_);
        }
        // attention -> ctx
        attn_kernel<<<B_ * NH_, 256, attn_smem>>>(pqkv, pwv, pctx);
        // attn_out = ctx @ out_w^T + b  (N=768, K=768) -> tmp
        {
            dim3 grid(H_ / 64, (MT + 63) / 64);
            gemm_nt_kernel<false><<<grid, 256>>>(pctx, out_w + (size_t)l * H_ * H_,
                                                 out_b + (size_t)l * H_, ptmp,
                                                 MT, H_, H_);
        }
        // x = LN1(x + attn_out)
        add_ln_kernel<<<MT, 256>>>(px, ptmp, ln1_s + (size_t)l * H_, ln1_b + (size_t)l * H_);
        // h1 = relu(x @ ff1_w^T + b)  (N=2048, K=768) -> tmp
        {
            dim3 grid(FF_ / 64, (MT + 63) / 64);
            gemm_nt_kernel<true><<<grid, 256>>>(px, ff1_w + (size_t)l * FF_ * H_,
                                                ff1_b + (size_t)l * FF_, ptmp,
                                                MT, FF_, H_);
        }
        // ff_out = h1 @ ff2_w^T + b   (N=768, K=2048) -> ctx
        {
            dim3 grid(H_ / 64, (MT + 63) / 64);
            gemm_nt_kernel<false><<<grid, 256>>>(ptmp, ff2_w + (size_t)l * H_ * FF_,
                                                 ff2_b + (size_t)l * H_, pctx,
                                                 MT, H_, FF_);
        }
        // x = LN2(x + ff_out)
        add_ln_kernel<<<MT, 256>>>(px, pctx, ln2_s + (size_t)l * H_, ln2_b + (size_t)l * H_);
    }

    cls_kernel<<<B_, 256>>>(px, cls_w, cls_b, out);
}

// round 10
// speedup vs baseline: 1.7474x; 1.7474x over previous
#include <cuda_runtime.h>
#include <cuda_bf16.h>
#include <math.h>

// ---------------- problem constants ----------------
#define B_    32
#define S_    512
#define H_    768
#define W_    128
#define G_    4
#define NH_   4
#define HD_   192
#define FF_   2048
#define NL_   2
#define NLAB_ 6
#define LW    129           // W + 1
#define MT    (B_ * LW)     // 4128 total rows
#define EPS_  1e-5f

// ---------------- scratch (no cudaMalloc allowed) ----------------
__device__ float g_x  [(size_t)MT * H_];
__device__ float g_qkv[(size_t)MT * 3 * H_];
__device__ float g_tmp[(size_t)MT * FF_];
__device__ float g_ctx[(size_t)MT * H_];
__device__ float g_gm [(size_t)B_ * W_ * G_];
__device__ float g_wv [(size_t)B_ * W_];

// ---------------- mask dtype auto-detect + normalize ----------------
__device__ __forceinline__ int classify_mode(unsigned int mx) {
    if (mx <= 1u) return 0;            // int32
    if (mx >= 0x3F000000u) return 2;   // float32
    return 1;                          // uint8
}
__device__ __forceinline__ float decode_mask(const void* p, int i, int mode) {
    if (mode == 0) return (float)((const int*)p)[i];
    if (mode == 1) return (float)((const unsigned char*)p)[i];
    return ((const float*)p)[i];
}

__global__ void norm_mask_kernel(const void* __restrict__ gm_raw,
                                 const void* __restrict__ wv_raw,
                                 float* __restrict__ gm,
                                 float* __restrict__ wv)
{
    __shared__ unsigned int smx[2];
    __shared__ unsigned int red[8];
    int tid = threadIdx.x, lane = tid & 31, w = tid >> 5;

    for (int which = 0; which < 2; which++) {
        const unsigned int* p = (const unsigned int*)(which ? wv_raw : gm_raw);
        int nw = which ? 1024 : 4096;
        unsigned int mx = 0;
        for (int i = tid; i < nw; i += 256) mx = max(mx, p[i]);
#pragma unroll
        for (int o = 16; o > 0; o >>= 1)
            mx = max(mx, __shfl_xor_sync(0xffffffffu, mx, o));
        if (lane == 0) red[w] = mx;
        __syncthreads();
        if (tid == 0) {
            unsigned int m = 0;
#pragma unroll
            for (int i = 0; i < 8; i++) m = max(m, red[i]);
            smx[which] = m;
        }
        __syncthreads();
    }
    int mode_g = classify_mode(smx[0]);
    int mode_w = classify_mode(smx[1]);

    for (int i = tid; i < B_ * W_ * G_; i += 256)
        gm[i] = decode_mask(gm_raw, i, mode_g);
    for (int i = tid; i < B_ * W_; i += 256)
        wv[i] = decode_mask(wv_raw, i, mode_w);
}

// ---------------- build x = [cls ; wordemb] ----------------
__global__ void build_x_kernel(const float* __restrict__ hidden,
                               const int*   __restrict__ idx,
                               const float* __restrict__ gmask,
                               const float* __restrict__ wvalid,
                               float* __restrict__ x)
{
    int row = blockIdx.x;
    int b = row / LW, r = row % LW;
    const float* hb = hidden + (size_t)b * S_ * H_;
    float* xr = x + (size_t)row * H_;
    int tid = threadIdx.x;

    if (r == 0) {
        for (int c = tid; c < H_; c += blockDim.x) xr[c] = hb[c];
        return;
    }
    int w = r - 1;
    bool valid = wvalid[b * W_ + w] > 0.5f;
    const int*   ig = idx   + ((size_t)(b * W_ + w)) * G_;
    const float* mg = gmask + ((size_t)(b * W_ + w)) * G_;

    int   t[G_];
    bool  use[G_];
    float cnt = 0.f;
#pragma unroll
    for (int g = 0; g < G_; g++) {
        use[g] = mg[g] > 0.5f;
        t[g]   = ig[g];
        cnt   += use[g] ? 1.f : 0.f;
    }
    float inv = valid ? (1.f / fmaxf(cnt, 1.f)) : 0.f;
    for (int c = tid; c < H_; c += blockDim.x) {
        float s = 0.f;
#pragma unroll
        for (int g = 0; g < G_; g++)
            if (use[g]) s += hb[(size_t)t[g] * H_ + c];
        xr[c] = s * inv;
    }
}

// ---------------- GEMM: C[M,N] = A[M,K] @ Wt[N,K]^T + bias (opt relu) ----------------
// 128x64 tile, BK=16, 256 threads, 8x4 register block, float4 smem reads,
// register-staged prefetch double buffering.
template <bool RELU>
__global__ void __launch_bounds__(256)
gemm_nt_kernel(const float* __restrict__ A, const float* __restrict__ Wt,
               const float* __restrict__ bias, float* __restrict__ C,
               int M, int N, int K)
{
    __shared__ float sA[16][132];   // [k][m], padded
    __shared__ float sB[16][68];    // [k][n], padded

    int tid = threadIdx.x;
    int m0 = blockIdx.y * 128;
    int n0 = blockIdx.x * 64;

    // global-load mapping (float4 along K)
    int kx4 = (tid & 3) * 4;        // k offset 0,4,8,12
    int rsel = tid >> 2;            // 0..63

    // compute mapping
    int tx = tid & 15;              // n quad: 4 cols each
    int ty = tid >> 4;              // m octet: 8 rows each

    float ra[2][4];                 // staged A (2 rows x float4)
    float rb[4];                    // staged B (1 row x float4)

    // initial stage (k0 = 0)
#pragma unroll
    for (int r = 0; r < 2; r++) {
        int m = m0 + rsel + r * 64;
        if (m < M) {
            float4 v = *(const float4*)&A[(size_t)m * K + kx4];
            ra[r][0] = v.x; ra[r][1] = v.y; ra[r][2] = v.z; ra[r][3] = v.w;
        } else {
            ra[r][0] = ra[r][1] = ra[r][2] = ra[r][3] = 0.f;
        }
    }
    {
        float4 v = *(const float4*)&Wt[(size_t)(n0 + rsel) * K + kx4];
        rb[0] = v.x; rb[1] = v.y; rb[2] = v.z; rb[3] = v.w;
    }

    float acc[8][4];
#pragma unroll
    for (int i = 0; i < 8; i++)
#pragma unroll
        for (int j = 0; j < 4; j++) acc[i][j] = 0.f;

    for (int k0 = 0;; k0 += 16) {
        // commit staged regs to smem
#pragma unroll
        for (int r = 0; r < 2; r++)
#pragma unroll
            for (int i = 0; i < 4; i++)
                sA[kx4 + i][rsel + r * 64] = ra[r][i];
#pragma unroll
        for (int i = 0; i < 4; i++)
            sB[kx4 + i][rsel] = rb[i];
        __syncthreads();

        bool more = (k0 + 16 < K);
        if (more) {
            int kb = k0 + 16 + kx4;
#pragma unroll
            for (int r = 0; r < 2; r++) {
                int m = m0 + rsel + r * 64;
                if (m < M) {
                    float4 v = *(const float4*)&A[(size_t)m * K + kb];
                    ra[r][0] = v.x; ra[r][1] = v.y; ra[r][2] = v.z; ra[r][3] = v.w;
                } else {
                    ra[r][0] = ra[r][1] = ra[r][2] = ra[r][3] = 0.f;
                }
            }
            float4 v = *(const float4*)&Wt[(size_t)(n0 + rsel) * K + kb];
            rb[0] = v.x; rb[1] = v.y; rb[2] = v.z; rb[3] = v.w;
        }

#pragma unroll
        for (int k = 0; k < 16; k++) {
            float4 a0 = *(const float4*)&sA[k][ty * 8];
            float4 a1 = *(const float4*)&sA[k][ty * 8 + 4];
            float4 b0 = *(const float4*)&sB[k][tx * 4];
            float av[8] = {a0.x, a0.y, a0.z, a0.w, a1.x, a1.y, a1.z, a1.w};
            float bv[4] = {b0.x, b0.y, b0.z, b0.w};
#pragma unroll
            for (int i = 0; i < 8; i++)
#pragma unroll
                for (int j = 0; j < 4; j++) acc[i][j] += av[i] * bv[j];
        }
        if (!more) break;
        __syncthreads();
    }

    // epilogue
    float4 bv = *(const float4*)&bias[n0 + tx * 4];
    float bb[4] = {bv.x, bv.y, bv.z, bv.w};
#pragma unroll
    for (int i = 0; i < 8; i++) {
        int m = m0 + ty * 8 + i;
        if (m >= M) continue;
        float4 o;
        o.x = acc[i][0] + bb[0];
        o.y = acc[i][1] + bb[1];
        o.z = acc[i][2] + bb[2];
        o.w = acc[i][3] + bb[3];
        if (RELU) {
            o.x = fmaxf(o.x, 0.f); o.y = fmaxf(o.y, 0.f);
            o.z = fmaxf(o.z, 0.f); o.w = fmaxf(o.w, 0.f);
        }
        *(float4*)&C[(size_t)m * N + n0 + tx * 4] = o;
    }
}

// ---------------- attention v2: grid (B*NH, 4 q-chunks), 2 q rows / warp ----------------
#define QCHUNK 33
#define ATTN_SMEM_FLOATS (2 * LW * HD_ + 16 * HD_ + 16 * 132)
__global__ void __launch_bounds__(256)
attn_kernel(const float* __restrict__ qkv,
            const float* __restrict__ wvalid,
            float* __restrict__ ctx)
{
    extern __shared__ float sm[];
    float* sK = sm;                          // [129][192]
    float* sV = sK + LW * HD_;               // [129][192]
    float* sQ = sV + LW * HD_;               // [8 warps][2][192]
    float* sS = sQ + 16 * HD_;               // [8 warps][2][132]
    __shared__ float sMask[LW];

    int bh = blockIdx.x;
    int b = bh / NH_, h = bh % NH_;
    int qt = blockIdx.y;
    int qstart = qt * QCHUNK;
    int qend = min(qstart + QCHUNK, LW);

    int tid = threadIdx.x;
    const float* base = qkv + (size_t)b * LW * (3 * H_);
    const float scale = rsqrtf((float)HD_);

    for (int i = tid; i < LW * HD_; i += 256) {
        int t = i / HD_, d = i - t * HD_;
        size_t off = (size_t)t * (3 * H_) + h * HD_ + d;
        sK[i] = base[off + H_];
        sV[i] = base[off + 2 * H_];
    }
    if (tid < LW)
        sMask[tid] = (tid == 0 || wvalid[b * W_ + tid - 1] > 0.5f) ? 0.f : -1e30f;
    __syncthreads();

    int warp = tid >> 5, lane = tid & 31;
    float* sq0 = sQ + warp * 2 * HD_;
    float* sq1 = sq0 + HD_;
    float* sr0 = sS + warp * 2 * 132;
    float* sr1 = sr0 + 132;
    const float2* sV2 = (const float2*)sV;

    for (int q0 = qstart + warp * 2; q0 < qend; q0 += 16) {
        bool has1 = (q0 + 1 < qend);
        int q1 = has1 ? q0 + 1 : q0;

        const float* qv0 = base + (size_t)q0 * (3 * H_) + h * HD_;
        const float* qv1 = base + (size_t)q1 * (3 * H_) + h * HD_;
        for (int d = lane; d < HD_; d += 32) {
            sq0[d] = qv0[d];
            sq1[d] = qv1[d];
        }
        __syncwarp();

        // ---- scores for both rows ----
        const float4* sq04 = (const float4*)sq0;
        const float4* sq14 = (const float4*)sq1;
        for (int k = lane; k < LW; k += 32) {
            const float4* kv4 = (const float4*)(sK + k * HD_);
            float s0 = 0.f, s1 = 0.f;
#pragma unroll 8
            for (int d4 = 0; d4 < HD_ / 4; d4++) {
                float4 c = kv4[d4];
                float4 a0 = sq04[d4];
                float4 a1 = sq14[d4];
                s0 += a0.x * c.x + a0.y * c.y + a0.z * c.z + a0.w * c.w;
                s1 += a1.x * c.x + a1.y * c.y + a1.z * c.z + a1.w * c.w;
            }
            float mk = sMask[k];
            sr0[k] = s0 * scale + mk;
            sr1[k] = s1 * scale + mk;
        }
        __syncwarp();

        // ---- softmax row 0 ----
        float mx0 = -1e30f, mx1 = -1e30f;
        for (int k = lane; k < LW; k += 32) {
            mx0 = fmaxf(mx0, sr0[k]);
            mx1 = fmaxf(mx1, sr1[k]);
        }
#pragma unroll
        for (int o = 16; o > 0; o >>= 1) {
            mx0 = fmaxf(mx0, __shfl_xor_sync(0xffffffffu, mx0, o));
            mx1 = fmaxf(mx1, __shfl_xor_sync(0xffffffffu, mx1, o));
        }
        float sum0 = 0.f, sum1 = 0.f;
        for (int k = lane; k < LW; k += 32) {
            float e0 = __expf(sr0[k] - mx0);
            float e1 = __expf(sr1[k] - mx1);
            sr0[k] = e0; sr1[k] = e1;
            sum0 += e0; sum1 += e1;
        }
#pragma unroll
        for (int o = 16; o > 0; o >>= 1) {
            sum0 += __shfl_xor_sync(0xffffffffu, sum0, o);
            sum1 += __shfl_xor_sync(0xffffffffu, sum1, o);
        }
        float inv0 = 1.f / sum0;
        float inv1 = 1.f / sum1;
        __syncwarp();

        // ---- ctx = a @ V (both rows share V reads) ----
        float2 acc0[3], acc1[3];
#pragma unroll
        for (int i = 0; i < 3; i++) {
            acc0[i] = make_float2(0.f, 0.f);
            acc1[i] = make_float2(0.f, 0.f);
        }
#pragma unroll 2
        for (int k = 0; k < LW; k++) {
            float s0 = sr0[k];
            float s1 = sr1[k];
            const float2* vr = sV2 + k * (HD_ / 2);
#pragma unroll
            for (int i = 0; i < 3; i++) {
                float2 v = vr[lane + 32 * i];
                acc0[i].x += s0 * v.x; acc0[i].y += s0 * v.y;
                acc1[i].x += s1 * v.x; acc1[i].y += s1 * v.y;
            }
        }
        float2* out0 = (float2*)(ctx + (size_t)(b * LW + q0) * H_ + h * HD_);
#pragma unroll
        for (int i = 0; i < 3; i++)
            out0[lane + 32 * i] = make_float2(acc0[i].x * inv0, acc0[i].y * inv0);
        if (has1) {
            float2* out1 = (float2*)(ctx + (size_t)(b * LW + q1) * H_ + h * HD_);
#pragma unroll
            for (int i = 0; i < 3; i++)
                out1[lane + 32 * i] = make_float2(acc1[i].x * inv1, acc1[i].y * inv1);
        }
        __syncwarp();
    }
}

// ---------------- fused residual-add + layernorm (in-place into x) ----------------
__global__ void __launch_bounds__(256)
add_ln_kernel(float* __restrict__ x, const float* __restrict__ y,
              const float* __restrict__ s, const float* __restrict__ bb)
{
    __shared__ float red[32];
    int row = blockIdx.x, tid = threadIdx.x;
    float* xr = x + (size_t)row * H_;
    const float* yr = y + (size_t)row * H_;

    float h[3];
    float sum = 0.f;
#pragma unroll
    for (int i = 0; i < 3; i++) {
        int c = tid + i * 256;
        h[i] = xr[c] + yr[c];
        sum += h[i];
    }
    int lane = tid & 31, w = tid >> 5;
#pragma unroll
    for (int o = 16; o > 0; o >>= 1) sum += __shfl_xor_sync(0xffffffffu, sum, o);
    if (lane == 0) red[w] = sum;
    __syncthreads();
    if (w == 0) {
        float v = (lane < 8) ? red[lane] : 0.f;
#pragma unroll
        for (int o = 4; o > 0; o >>= 1) v += __shfl_xor_sync(0xffu, v, o);
        if (lane == 0) red[0] = v;
    }
    __syncthreads();
    float mean = red[0] * (1.f / H_);
    __syncthreads();

    float vs = 0.f;
#pragma unroll
    for (int i = 0; i < 3; i++) {
        float d = h[i] - mean;
        vs += d * d;
    }
#pragma unroll
    for (int o = 16; o > 0; o >>= 1) vs += __shfl_xor_sync(0xffffffffu, vs, o);
    if (lane == 0) red[w] = vs;
    __syncthreads();
    if (w == 0) {
        float v = (lane < 8) ? red[lane] : 0.f;
#pragma unroll
        for (int o = 4; o > 0; o >>= 1) v += __shfl_xor_sync(0xffu, v, o);
        if (lane == 0) red[0] = v;
    }
    __syncthreads();
    float var = red[0] * (1.f / H_);
    float rstd = rsqrtf(var + EPS_);

#pragma unroll
    for (int i = 0; i < 3; i++) {
        int c = tid + i * 256;
        xr[c] = (h[i] - mean) * rstd * s[c] + bb[c];
    }
}

// ---------------- classifier head + pooled copy ----------------
__global__ void __launch_bounds__(256)
cls_kernel(const float* __restrict__ x, const float* __restrict__ cw,
           const float* __restrict__ cb, float* __restrict__ out)
{
    int b = blockIdx.x, tid = threadIdx.x;
    const float* p = x + (size_t)b * LW * H_;
    float* pooled = out + NLAB_ * B_ + (size_t)b * H_;
    for (int c = tid; c < H_; c += 256) pooled[c] = p[c];

    int warp = tid >> 5, lane = tid & 31;
    if (warp < NLAB_) {
        float s = 0.f;
        for (int c = lane; c < H_; c += 32) s += p[c] * cw[(size_t)warp * H_ + c];
#pragma unroll
        for (int o = 16; o > 0; o >>= 1) s += __shfl_xor_sync(0xffffffffu, s, o);
        if (lane == 0) out[b * NLAB_ + warp] = s + cb[warp];
    }
}

// ---------------- launcher ----------------
extern "C" void kernel_launch(void* const* d_in, const int* in_sizes, int n_in,
                              void* d_out, int out_size)
{
    const float* hidden = (const float*)d_in[0];
    const int*   widx   = (const int*)d_in[1];
    const void*  gmask  = (const void*)d_in[2];
    const void*  wvalid = (const void*)d_in[3];
    const float* qkv_w = (const float*)d_in[4];
    const float* qkv_b = (const float*)d_in[5];
    const float* out_w = (const float*)d_in[6];
    const float* out_b = (const float*)d_in[7];
    const float* ff1_w = (const float*)d_in[8];
    const float* ff1_b = (const float*)d_in[9];
    const float* ff2_w = (const float*)d_in[10];
    const float* ff2_b = (const float*)d_in[11];
    const float* ln1_s = (const float*)d_in[12];
    const float* ln1_b = (const float*)d_in[13];
    const float* ln2_s = (const float*)d_in[14];
    const float* ln2_b = (const float*)d_in[15];
    const float* cls_w = (const float*)d_in[16];
    const float* cls_b = (const float*)d_in[17];
    float* out = (float*)d_out;

    float *px, *pqkv, *ptmp, *pctx, *pgm, *pwv;
    cudaGetSymbolAddress((void**)&px,   g_x);
    cudaGetSymbolAddress((void**)&pqkv, g_qkv);
    cudaGetSymbolAddress((void**)&ptmp, g_tmp);
    cudaGetSymbolAddress((void**)&pctx, g_ctx);
    cudaGetSymbolAddress((void**)&pgm,  g_gm);
    cudaGetSymbolAddress((void**)&pwv,  g_wv);

    const int attn_smem = ATTN_SMEM_FLOATS * (int)sizeof(float);
    cudaFuncSetAttribute(attn_kernel, cudaFuncAttributeMaxDynamicSharedMemorySize, attn_smem);

    norm_mask_kernel<<<1, 256>>>(gmask, wvalid, pgm, pwv);
    build_x_kernel<<<MT, 256>>>(hidden, widx, pgm, pwv, px);

    const int MTILES = (MT + 127) / 128;
    for (int l = 0; l < NL_; l++) {
        // qkv = x @ qkv_w^T + b     (M=4128, N=2304, K=768)
        {
            dim3 grid(3 * H_ / 64, MTILES);
            gemm_nt_kernel<false><<<grid, 256>>>(px, qkv_w + (size_t)l * 3 * H_ * H_,
                                                 qkv_b + (size_t)l * 3 * H_, pqkv,
                                                 MT, 3 * H_, H_);
        }
        // attention -> ctx
        {
            dim3 grid(B_ * NH_, 4);
            attn_kernel<<<grid, 256, attn_smem>>>(pqkv, pwv, pctx);
        }
        // attn_out = ctx @ out_w^T + b  (N=768, K=768) -> tmp
        {
            dim3 grid(H_ / 64, MTILES);
            gemm_nt_kernel<false><<<grid, 256>>>(pctx, out_w + (size_t)l * H_ * H_,
                                                 out_b + (size_t)l * H_, ptmp,
                                                 MT, H_, H_);
        }
        // x = LN1(x + attn_out)
        add_ln_kernel<<<MT, 256>>>(px, ptmp, ln1_s + (size_t)l * H_, ln1_b + (size_t)l * H_);
        // h1 = relu(x @ ff1_w^T + b)  (N=2048, K=768) -> tmp
        {
            dim3 grid(FF_ / 64, MTILES);
            gemm_nt_kernel<true><<<grid, 256>>>(px, ff1_w + (size_t)l * FF_ * H_,
                                                ff1_b + (size_t)l * FF_, ptmp,
                                                MT, FF_, H_);
        }
        // ff_out = h1 @ ff2_w^T + b   (N=768, K=2048) -> ctx
        {
            dim3 grid(H_ / 64, MTILES);
            gemm_nt_kernel<false><<<grid, 256>>>(ptmp, ff2_w + (size_t)l * H_ * FF_,
                                                 ff2_b + (size_t)l * H_, pctx,
                                                 MT, H_, FF_);
        }
        // x = LN2(x + ff_out)
        add_ln_kernel<<<MT, 256>>>(px, pctx, ln2_s + (size_t)l * H_, ln2_b + (size_t)l * H_);
    }

    cls_kernel<<<B_, 256>>>(px, cls_w, cls_b, out);
}

// round 12
// speedup vs baseline: 1.7938x; 1.0265x over previous
#include <cuda_runtime.h>
#include <cuda_bf16.h>
#include <math.h>

// ---------------- problem constants ----------------
#define B_    32
#define S_    512
#define H_    768
#define W_    128
#define G_    4
#define NH_   4
#define HD_   192
#define FF_   2048
#define NL_   2
#define NLAB_ 6
#define LW    129           // W + 1
#define MT    (B_ * LW)     // 4128 total rows
#define SLD   132           // padded score row length
#define EPS_  1e-5f

// ---------------- scratch (no cudaMalloc allowed) ----------------
__device__ float g_x  [(size_t)MT * H_];
__device__ float g_qkv[(size_t)MT * 3 * H_];
__device__ float g_tmp[(size_t)MT * FF_];     // scores (B*NH*129*132) alias + ff1 out + attn_out
__device__ float g_ctx[(size_t)MT * H_];
__device__ float g_gm [(size_t)B_ * W_ * G_];
__device__ float g_wv [(size_t)B_ * W_];

// ---------------- mask dtype auto-detect + normalize ----------------
__device__ __forceinline__ int classify_mode(unsigned int mx) {
    if (mx <= 1u) return 0;            // int32
    if (mx >= 0x3F000000u) return 2;   // float32
    return 1;                          // uint8
}
__device__ __forceinline__ float decode_mask(const void* p, int i, int mode) {
    if (mode == 0) return (float)((const int*)p)[i];
    if (mode == 1) return (float)((const unsigned char*)p)[i];
    return ((const float*)p)[i];
}

__global__ void norm_mask_kernel(const void* __restrict__ gm_raw,
                                 const void* __restrict__ wv_raw,
                                 float* __restrict__ gm,
                                 float* __restrict__ wv)
{
    __shared__ unsigned int smx[2];
    __shared__ unsigned int red[8];
    int tid = threadIdx.x, lane = tid & 31, w = tid >> 5;

    for (int which = 0; which < 2; which++) {
        const unsigned int* p = (const unsigned int*)(which ? wv_raw : gm_raw);
        int nw = which ? 1024 : 4096;
        unsigned int mx = 0;
        for (int i = tid; i < nw; i += 256) mx = max(mx, p[i]);
#pragma unroll
        for (int o = 16; o > 0; o >>= 1)
            mx = max(mx, __shfl_xor_sync(0xffffffffu, mx, o));
        if (lane == 0) red[w] = mx;
        __syncthreads();
        if (tid == 0) {
            unsigned int m = 0;
#pragma unroll
            for (int i = 0; i < 8; i++) m = max(m, red[i]);
            smx[which] = m;
        }
        __syncthreads();
    }
    int mode_g = classify_mode(smx[0]);
    int mode_w = classify_mode(smx[1]);

    for (int i = tid; i < B_ * W_ * G_; i += 256)
        gm[i] = decode_mask(gm_raw, i, mode_g);
    for (int i = tid; i < B_ * W_; i += 256)
        wv[i] = decode_mask(wv_raw, i, mode_w);
}

// ---------------- build x = [cls ; wordemb] ----------------
__global__ void build_x_kernel(const float* __restrict__ hidden,
                               const int*   __restrict__ idx,
                               const float* __restrict__ gmask,
                               const float* __restrict__ wvalid,
                               float* __restrict__ x)
{
    int row = blockIdx.x;
    int b = row / LW, r = row % LW;
    const float* hb = hidden + (size_t)b * S_ * H_;
    float* xr = x + (size_t)row * H_;
    int tid = threadIdx.x;

    if (r == 0) {
        for (int c = tid; c < H_; c += blockDim.x) xr[c] = hb[c];
        return;
    }
    int w = r - 1;
    bool valid = wvalid[b * W_ + w] > 0.5f;
    const int*   ig = idx   + ((size_t)(b * W_ + w)) * G_;
    const float* mg = gmask + ((size_t)(b * W_ + w)) * G_;

    int   t[G_];
    bool  use[G_];
    float cnt = 0.f;
#pragma unroll
    for (int g = 0; g < G_; g++) {
        use[g] = mg[g] > 0.5f;
        t[g]   = ig[g];
        cnt   += use[g] ? 1.f : 0.f;
    }
    float inv = valid ? (1.f / fmaxf(cnt, 1.f)) : 0.f;
    for (int c = tid; c < H_; c += blockDim.x) {
        float s = 0.f;
#pragma unroll
        for (int g = 0; g < G_; g++)
            if (use[g]) s += hb[(size_t)t[g] * H_ + c];
        xr[c] = s * inv;
    }
}

// ---------------- GEMM: C[M,N] = A[M,K] @ Wt[N,K]^T + bias (opt relu) ----------------
// 128x128 tile, BK=16, 256 threads, 8x8 per thread (split 4+4 fragments),
// conflict-free float4 smem reads, register-staged prefetch.
template <bool RELU>
__global__ void __launch_bounds__(256)
gemm_nt_kernel(const float* __restrict__ A, const float* __restrict__ Wt,
               const float* __restrict__ bias, float* __restrict__ C,
               int M, int N, int K)
{
    __shared__ float sA[16][132];   // [k][m]
    __shared__ float sB[16][132];   // [k][n]

    int tid = threadIdx.x;
    int m0 = blockIdx.y * 128;
    int n0 = blockIdx.x * 128;

    int kx4 = (tid & 3) * 4;        // k offset 0,4,8,12
    int rsel = tid >> 2;            // 0..63

    int tx = tid & 15;              // n fragment: cols tx*4 and tx*4+64
    int ty = tid >> 4;              // m fragment: rows ty*4 and ty*4+64

    float ra[2][4], rb[2][4];

    // initial stage (k0 = 0)
#pragma unroll
    for (int r = 0; r < 2; r++) {
        int m = m0 + rsel + r * 64;
        if (m < M) {
            float4 v = *(const float4*)&A[(size_t)m * K + kx4];
            ra[r][0] = v.x; ra[r][1] = v.y; ra[r][2] = v.z; ra[r][3] = v.w;
        } else {
            ra[r][0] = ra[r][1] = ra[r][2] = ra[r][3] = 0.f;
        }
        float4 v = *(const float4*)&Wt[(size_t)(n0 + rsel + r * 64) * K + kx4];
        rb[r][0] = v.x; rb[r][1] = v.y; rb[r][2] = v.z; rb[r][3] = v.w;
    }

    float acc[2][2][4][4];
#pragma unroll
    for (int p = 0; p < 2; p++)
#pragma unroll
        for (int q = 0; q < 2; q++)
#pragma unroll
            for (int i = 0; i < 4; i++)
#pragma unroll
                for (int j = 0; j < 4; j++) acc[p][q][i][j] = 0.f;

    for (int k0 = 0;; k0 += 16) {
#pragma unroll
        for (int r = 0; r < 2; r++)
#pragma unroll
            for (int i = 0; i < 4; i++) {
                sA[kx4 + i][rsel + r * 64] = ra[r][i];
                sB[kx4 + i][rsel + r * 64] = rb[r][i];
            }
        __syncthreads();

        bool more = (k0 + 16 < K);
        if (more) {
            int kb = k0 + 16 + kx4;
#pragma unroll
            for (int r = 0; r < 2; r++) {
                int m = m0 + rsel + r * 64;
                if (m < M) {
                    float4 v = *(const float4*)&A[(size_t)m * K + kb];
                    ra[r][0] = v.x; ra[r][1] = v.y; ra[r][2] = v.z; ra[r][3] = v.w;
                } else {
                    ra[r][0] = ra[r][1] = ra[r][2] = ra[r][3] = 0.f;
                }
                float4 v = *(const float4*)&Wt[(size_t)(n0 + rsel + r * 64) * K + kb];
                rb[r][0] = v.x; rb[r][1] = v.y; rb[r][2] = v.z; rb[r][3] = v.w;
            }
        }

#pragma unroll
        for (int k = 0; k < 16; k++) {
            float4 a0 = *(const float4*)&sA[k][ty * 4];
            float4 a1 = *(const float4*)&sA[k][ty * 4 + 64];
            float4 b0 = *(const float4*)&sB[k][tx * 4];
            float4 b1 = *(const float4*)&sB[k][tx * 4 + 64];
            float av[2][4] = {{a0.x, a0.y, a0.z, a0.w}, {a1.x, a1.y, a1.z, a1.w}};
            float bv[2][4] = {{b0.x, b0.y, b0.z, b0.w}, {b1.x, b1.y, b1.z, b1.w}};
#pragma unroll
            for (int p = 0; p < 2; p++)
#pragma unroll
                for (int q = 0; q < 2; q++)
#pragma unroll
                    for (int i = 0; i < 4; i++)
#pragma unroll
                        for (int j = 0; j < 4; j++)
                            acc[p][q][i][j] += av[p][i] * bv[q][j];
        }
        if (!more) break;
        __syncthreads();
    }

    // epilogue
#pragma unroll
    for (int q = 0; q < 2; q++) {
        float4 bv = *(const float4*)&bias[n0 + q * 64 + tx * 4];
        float bb[4] = {bv.x, bv.y, bv.z, bv.w};
#pragma unroll
        for (int p = 0; p < 2; p++)
#pragma unroll
            for (int i = 0; i < 4; i++) {
                int m = m0 + p * 64 + ty * 4 + i;
                if (m >= M) continue;
                float4 o;
                o.x = acc[p][q][i][0] + bb[0];
                o.y = acc[p][q][i][1] + bb[1];
                o.z = acc[p][q][i][2] + bb[2];
                o.w = acc[p][q][i][3] + bb[3];
                if (RELU) {
                    o.x = fmaxf(o.x, 0.f); o.y = fmaxf(o.y, 0.f);
                    o.z = fmaxf(o.z, 0.f); o.w = fmaxf(o.w, 0.f);
                }
                *(float4*)&C[(size_t)m * N + n0 + q * 64 + tx * 4] = o;
            }
    }
}

// ---------------- attention as batched GEMMs ----------------
// scores: S[bh][m][n] = (Q[m] . K[n]) * scale + mask[n], 64x64 tile, K=192
__global__ void __launch_bounds__(256)
attn_score_kernel(const float* __restrict__ qkv,
                  const float* __restrict__ wvalid,
                  float* __restrict__ S)
{
    __shared__ float sA[16][72];
    __shared__ float sB[16][72];

    int bh = blockIdx.z, b = bh >> 2, h = bh & 3;
    int m0 = blockIdx.y * 64, n0 = blockIdx.x * 64;
    const float* Q  = qkv + (size_t)b * LW * (3 * H_) + h * HD_;
    const float* Kp = Q + H_;

    int tid = threadIdx.x;
    int kx4 = (tid & 3) * 4, rsel = tid >> 2;
    int tx = tid & 15, ty = tid >> 4;

    float acc[4][4];
#pragma unroll
    for (int i = 0; i < 4; i++)
#pragma unroll
        for (int j = 0; j < 4; j++) acc[i][j] = 0.f;

    for (int k0 = 0; k0 < HD_; k0 += 16) {
        int m = m0 + rsel, n = n0 + rsel;
        float4 a = make_float4(0.f, 0.f, 0.f, 0.f), bvv = a;
        if (m < LW) a   = *(const float4*)&Q [(size_t)m * (3 * H_) + k0 + kx4];
        if (n < LW) bvv = *(const float4*)&Kp[(size_t)n * (3 * H_) + k0 + kx4];
        sA[kx4 + 0][rsel] = a.x;  sA[kx4 + 1][rsel] = a.y;
        sA[kx4 + 2][rsel] = a.z;  sA[kx4 + 3][rsel] = a.w;
        sB[kx4 + 0][rsel] = bvv.x; sB[kx4 + 1][rsel] = bvv.y;
        sB[kx4 + 2][rsel] = bvv.z; sB[kx4 + 3][rsel] = bvv.w;
        __syncthreads();
#pragma unroll
        for (int k = 0; k < 16; k++) {
            float4 a4 = *(const float4*)&sA[k][ty * 4];
            float4 b4 = *(const float4*)&sB[k][tx * 4];
            float av[4] = {a4.x, a4.y, a4.z, a4.w};
            float bw[4] = {b4.x, b4.y, b4.z, b4.w};
#pragma unroll
            for (int i = 0; i < 4; i++)
#pragma unroll
                for (int j = 0; j < 4; j++) acc[i][j] += av[i] * bw[j];
        }
        __syncthreads();
    }

    const float scale = rsqrtf((float)HD_);
    float* Sb = S + (size_t)bh * LW * SLD;
#pragma unroll
    for (int j = 0; j < 4; j++) {
        int n = n0 + tx * 4 + j;
        if (n >= LW) continue;
        float mask = (n == 0 || wvalid[b * W_ + n - 1] > 0.5f) ? 0.f : -1e30f;
#pragma unroll
        for (int i = 0; i < 4; i++) {
            int m = m0 + ty * 4 + i;
            if (m < LW) Sb[(size_t)m * SLD + n] = acc[i][j] * scale + mask;
        }
    }
}

// softmax over each score row; zero the pad columns so AV can run K over 132+.
__global__ void __launch_bounds__(256)
attn_softmax_kernel(float* __restrict__ S)
{
    int row = blockIdx.x * 8 + (threadIdx.x >> 5);
    if (row >= B_ * NH_ * LW) return;
    int lane = threadIdx.x & 31;
    float* p = S + (size_t)row * SLD;

    float mx = -1e30f;
    for (int k = lane; k < LW; k += 32) mx = fmaxf(mx, p[k]);
#pragma unroll
    for (int o = 16; o > 0; o >>= 1) mx = fmaxf(mx, __shfl_xor_sync(0xffffffffu, mx, o));
    float sum = 0.f;
    float e0 = 0.f, e1 = 0.f, e2 = 0.f, e3 = 0.f, e4 = 0.f;
    {
        int k = lane;
        e0 = __expf(p[k] - mx); sum += e0; k += 32;
        e1 = __expf(p[k] - mx); sum += e1; k += 32;
        e2 = __expf(p[k] - mx); sum += e2; k += 32;
        e3 = __expf(p[k] - mx); sum += e3; k += 32;
        if (k < LW) { e4 = __expf(p[k] - mx); sum += e4; }
    }
#pragma unroll
    for (int o = 16; o > 0; o >>= 1) sum += __shfl_xor_sync(0xffffffffu, sum, o);
    float inv = 1.f / sum;
    {
        int k = lane;
        p[k] = e0 * inv; k += 32;
        p[k] = e1 * inv; k += 32;
        p[k] = e2 * inv; k += 32;
        p[k] = e3 * inv; k += 32;
        if (k < SLD) p[k] = (k < LW) ? e4 * inv : 0.f;
    }
}

// AV: ctx[bh][m][n] = sum_k P[m][k] * V[k][n]   (NN gemm, M=129, N=192, K=129)
__global__ void __launch_bounds__(256)
attn_av_kernel(const float* __restrict__ S,
               const float* __restrict__ qkv,
               float* __restrict__ ctx)
{
    __shared__ float sA[16][72];   // [k][m] from P
    __shared__ float sB[16][72];   // [k][n] from V
    int bh = blockIdx.z, b = bh >> 2, h = bh & 3;
    int m0 = blockIdx.y * 64, n0 = blockIdx.x * 64;
    const float* P = S + (size_t)bh * LW * SLD;
    const float* V = qkv + (size_t)b * LW * (3 * H_) + 2 * H_ + h * HD_;

    int tid = threadIdx.x;
    int kx4 = (tid & 3) * 4, rsel = tid >> 2;   // P loads
    int ksel = tid >> 4, nx4 = (tid & 15) * 4;  // V loads
    int tx = tid & 15, ty = tid >> 4;

    float acc[4][4];
#pragma unroll
    for (int i = 0; i < 4; i++)
#pragma unroll
        for (int j = 0; j < 4; j++) acc[i][j] = 0.f;

    for (int k0 = 0; k0 < LW; k0 += 16) {
        int m = m0 + rsel;
        float4 a = make_float4(0.f, 0.f, 0.f, 0.f);
        if (m < LW && k0 + kx4 <= SLD - 4)
            a = *(const float4*)&P[(size_t)m * SLD + k0 + kx4];
        float4 bvv = make_float4(0.f, 0.f, 0.f, 0.f);
        int kr = k0 + ksel;
        if (kr < LW)
            bvv = *(const float4*)&V[(size_t)kr * (3 * H_) + n0 + nx4];
        sA[kx4 + 0][rsel] = a.x;  sA[kx4 + 1][rsel] = a.y;
        sA[kx4 + 2][rsel] = a.z;  sA[kx4 + 3][rsel] = a.w;
        *(float4*)&sB[ksel][nx4] = bvv;
        __syncthreads();
#pragma unroll
        for (int k = 0; k < 16; k++) {
            float4 a4 = *(const float4*)&sA[k][ty * 4];
            float4 b4 = *(const float4*)&sB[k][tx * 4];
            float av[4] = {a4.x, a4.y, a4.z, a4.w};
            float bw[4] = {b4.x, b4.y, b4.z, b4.w};
#pragma unroll
            for (int i = 0; i < 4; i++)
#pragma unroll
                for (int j = 0; j < 4; j++) acc[i][j] += av[i] * bw[j];
        }
        __syncthreads();
    }

#pragma unroll
    for (int i = 0; i < 4; i++) {
        int m = m0 + ty * 4 + i;
        if (m >= LW) continue;
        float4 o;
        o.x = acc[i][0]; o.y = acc[i][1]; o.z = acc[i][2]; o.w = acc[i][3];
        *(float4*)&ctx[(size_t)(b * LW + m) * H_ + h * HD_ + n0 + tx * 4] = o;
    }
}

// ---------------- fused residual-add + layernorm (in-place into x) ----------------
__global__ void __launch_bounds__(256)
add_ln_kernel(float* __restrict__ x, const float* __restrict__ y,
              const float* __restrict__ s, const float* __restrict__ bb)
{
    __shared__ float red[32];
    int row = blockIdx.x, tid = threadIdx.x;
    float* xr = x + (size_t)row * H_;
    const float* yr = y + (size_t)row * H_;

    float h[3];
    float sum = 0.f;
#pragma unroll
    for (int i = 0; i < 3; i++) {
        int c = tid + i * 256;
        h[i] = xr[c] + yr[c];
        sum += h[i];
    }
    int lane = tid & 31, w = tid >> 5;
#pragma unroll
    for (int o = 16; o > 0; o >>= 1) sum += __shfl_xor_sync(0xffffffffu, sum, o);
    if (lane == 0) red[w] = sum;
    __syncthreads();
    if (w == 0) {
        float v = (lane < 8) ? red[lane] : 0.f;
#pragma unroll
        for (int o = 4; o > 0; o >>= 1) v += __shfl_xor_sync(0xffu, v, o);
        if (lane == 0) red[0] = v;
    }
    __syncthreads();
    float mean = red[0] * (1.f / H_);
    __syncthreads();

    float vs = 0.f;
#pragma unroll
    for (int i = 0; i < 3; i++) {
        float d = h[i] - mean;
        vs += d * d;
    }
#pragma unroll
    for (int o = 16; o > 0; o >>= 1) vs += __shfl_xor_sync(0xffffffffu, vs, o);
    if (lane == 0) red[w] = vs;
    __syncthreads();
    if (w == 0) {
        float v = (lane < 8) ? red[lane] : 0.f;
#pragma unroll
        for (int o = 4; o > 0; o >>= 1) v += __shfl_xor_sync(0xffu, v, o);
        if (lane == 0) red[0] = v;
    }
    __syncthreads();
    float var = red[0] * (1.f / H_);
    float rstd = rsqrtf(var + EPS_);

#pragma unroll
    for (int i = 0; i < 3; i++) {
        int c = tid + i * 256;
        xr[c] = (h[i] - mean) * rstd * s[c] + bb[c];
    }
}

// ---------------- classifier head + pooled copy ----------------
__global__ void __launch_bounds__(256)
cls_kernel(const float* __restrict__ x, const float* __restrict__ cw,
           const float* __restrict__ cb, float* __restrict__ out)
{
    int b = blockIdx.x, tid = threadIdx.x;
    const float* p = x + (size_t)b * LW * H_;
    float* pooled = out + NLAB_ * B_ + (size_t)b * H_;
    for (int c = tid; c < H_; c += 256) pooled[c] = p[c];

    int warp = tid >> 5, lane = tid & 31;
    if (warp < NLAB_) {
        float s = 0.f;
        for (int c = lane; c < H_; c += 32) s += p[c] * cw[(size_t)warp * H_ + c];
#pragma unroll
        for (int o = 16; o > 0; o >>= 1) s += __shfl_xor_sync(0xffffffffu, s, o);
        if (lane == 0) out[b * NLAB_ + warp] = s + cb[warp];
    }
}

// ---------------- launcher ----------------
extern "C" void kernel_launch(void* const* d_in, const int* in_sizes, int n_in,
                              void* d_out, int out_size)
{
    const float* hidden = (const float*)d_in[0];
    const int*   widx   = (const int*)d_in[1];
    const void*  gmask  = (const void*)d_in[2];
    const void*  wvalid = (const void*)d_in[3];
    const float* qkv_w = (const float*)d_in[4];
    const float* qkv_b = (const float*)d_in[5];
    const float* out_w = (const float*)d_in[6];
    const float* out_b = (const float*)d_in[7];
    const float* ff1_w = (const float*)d_in[8];
    const float* ff1_b = (const float*)d_in[9];
    const float* ff2_w = (const float*)d_in[10];
    const float* ff2_b = (const float*)d_in[11];
    const float* ln1_s = (const float*)d_in[12];
    const float* ln1_b = (const float*)d_in[13];
    const float* ln2_s = (const float*)d_in[14];
    const float* ln2_b = (const float*)d_in[15];
    const float* cls_w = (const float*)d_in[16];
    const float* cls_b = (const float*)d_in[17];
    float* out = (float*)d_out;

    float *px, *pqkv, *ptmp, *pctx, *pgm, *pwv;
    cudaGetSymbolAddress((void**)&px,   g_x);
    cudaGetSymbolAddress((void**)&pqkv, g_qkv);
    cudaGetSymbolAddress((void**)&ptmp, g_tmp);
    cudaGetSymbolAddress((void**)&pctx, g_ctx);
    cudaGetSymbolAddress((void**)&pgm,  g_gm);
    cudaGetSymbolAddress((void**)&pwv,  g_wv);

    norm_mask_kernel<<<1, 256>>>(gmask, wvalid, pgm, pwv);
    build_x_kernel<<<MT, 256>>>(hidden, widx, pgm, pwv, px);

    const int MTILES = (MT + 127) / 128;   // 33
    const int SROWS = B_ * NH_ * LW;       // 16512
    for (int l = 0; l < NL_; l++) {
        // qkv = x @ qkv_w^T + b     (M=4128, N=2304, K=768)
        {
            dim3 grid(3 * H_ / 128, MTILES);
            gemm_nt_kernel<false><<<grid, 256>>>(px, qkv_w + (size_t)l * 3 * H_ * H_,
                                                 qkv_b + (size_t)l * 3 * H_, pqkv,
                                                 MT, 3 * H_, H_);
        }
        // attention: scores -> softmax -> AV
        {
            dim3 grid(3, 3, B_ * NH_);
            attn_score_kernel<<<grid, 256>>>(pqkv, pwv, ptmp);
            attn_softmax_kernel<<<(SROWS + 7) / 8, 256>>>(ptmp);
            dim3 gav(HD_ / 64, 3, B_ * NH_);
            attn_av_kernel<<<gav, 256>>>(ptmp, pqkv, pctx);
        }
        // attn_out = ctx @ out_w^T + b  (N=768, K=768) -> tmp
        {
            dim3 grid(H_ / 128, MTILES);
            gemm_nt_kernel<false><<<grid, 256>>>(pctx, out_w + (size_t)l * H_ * H_,
                                                 out_b + (size_t)l * H_, ptmp,
                                                 MT, H_, H_);
        }
        // x = LN1(x + attn_out)
        add_ln_kernel<<<MT, 256>>>(px, ptmp, ln1_s + (size_t)l * H_, ln1_b + (size_t)l * H_);
        // h1 = relu(x @ ff1_w^T + b)  (N=2048, K=768) -> tmp
        {
            dim3 grid(FF_ / 128, MTILES);
            gemm_nt_kernel<true><<<grid, 256>>>(px, ff1_w + (size_t)l * FF_ * H_,
                                                ff1_b + (size_t)l * FF_, ptmp,
                                                MT, FF_, H_);
        }
        // ff_out = h1 @ ff2_w^T + b   (N=768, K=2048) -> ctx
        {
            dim3 grid(H_ / 128, MTILES);
            gemm_nt_kernel<false><<<grid, 256>>>(ptmp, ff2_w + (size_t)l * H_ * FF_,
                                                 ff2_b + (size_t)l * H_, pctx,
                                                 MT, H_, FF_);
        }
        // x = LN2(x + ff_out)
        add_ln_kernel<<<MT, 256>>>(px, pctx, ln2_s + (size_t)l * H_, ln2_b + (size_t)l * H_);
    }

    cls_kernel<<<B_, 256>>>(px, cls_w, cls_b, out);
}

// round 13
// speedup vs baseline: 3.4937x; 1.9477x over previous
#include <cuda_runtime.h>
#include <cuda_bf16.h>
#include <math.h>

// ---------------- problem constants ----------------
#define B_    32
#define S_    512
#define H_    768
#define W_    128
#define G_    4
#define NH_   4
#define HD_   192
#define FF_   2048
#define NL_   2
#define NLAB_ 6
#define LW    129           // W + 1
#define MT    (B_ * LW)     // 4128 total rows
#define SLD   132           // padded score row length
#define EPS_  1e-5f

// ---------------- scratch (no cudaMalloc allowed) ----------------
__device__ float g_x  [(size_t)MT * H_];
__device__ float g_qkv[(size_t)MT * 3 * H_];
__device__ float g_tmp[(size_t)MT * FF_];     // scores alias + attn_out + ff1 out
__device__ float g_ctx[(size_t)MT * H_];
__device__ float g_gm [(size_t)B_ * W_ * G_];
__device__ float g_wv [(size_t)B_ * W_];

// ---------------- mask dtype auto-detect + normalize ----------------
__device__ __forceinline__ int classify_mode(unsigned int mx) {
    if (mx <= 1u) return 0;            // int32
    if (mx >= 0x3F000000u) return 2;   // float32
    return 1;                          // uint8
}
__device__ __forceinline__ float decode_mask(const void* p, int i, int mode) {
    if (mode == 0) return (float)((const int*)p)[i];
    if (mode == 1) return (float)((const unsigned char*)p)[i];
    return ((const float*)p)[i];
}

__global__ void norm_mask_kernel(const void* __restrict__ gm_raw,
                                 const void* __restrict__ wv_raw,
                                 float* __restrict__ gm,
                                 float* __restrict__ wv)
{
    __shared__ unsigned int smx[2];
    __shared__ unsigned int red[8];
    int tid = threadIdx.x, lane = tid & 31, w = tid >> 5;

    for (int which = 0; which < 2; which++) {
        const unsigned int* p = (const unsigned int*)(which ? wv_raw : gm_raw);
        int nw = which ? 1024 : 4096;
        unsigned int mx = 0;
        for (int i = tid; i < nw; i += 256) mx = max(mx, p[i]);
#pragma unroll
        for (int o = 16; o > 0; o >>= 1)
            mx = max(mx, __shfl_xor_sync(0xffffffffu, mx, o));
        if (lane == 0) red[w] = mx;
        __syncthreads();
        if (tid == 0) {
            unsigned int m = 0;
#pragma unroll
            for (int i = 0; i < 8; i++) m = max(m, red[i]);
            smx[which] = m;
        }
        __syncthreads();
    }
    int mode_g = classify_mode(smx[0]);
    int mode_w = classify_mode(smx[1]);

    for (int i = tid; i < B_ * W_ * G_; i += 256)
        gm[i] = decode_mask(gm_raw, i, mode_g);
    for (int i = tid; i < B_ * W_; i += 256)
        wv[i] = decode_mask(wv_raw, i, mode_w);
}

// ---------------- build x = [cls ; wordemb] ----------------
__global__ void build_x_kernel(const float* __restrict__ hidden,
                               const int*   __restrict__ idx,
                               const float* __restrict__ gmask,
                               const float* __restrict__ wvalid,
                               float* __restrict__ x)
{
    int row = blockIdx.x;
    int b = row / LW, r = row % LW;
    const float* hb = hidden + (size_t)b * S_ * H_;
    float* xr = x + (size_t)row * H_;
    int tid = threadIdx.x;

    if (r == 0) {
        for (int c = tid; c < H_; c += blockDim.x) xr[c] = hb[c];
        return;
    }
    int w = r - 1;
    bool valid = wvalid[b * W_ + w] > 0.5f;
    const int*   ig = idx   + ((size_t)(b * W_ + w)) * G_;
    const float* mg = gmask + ((size_t)(b * W_ + w)) * G_;

    int   t[G_];
    bool  use[G_];
    float cnt = 0.f;
#pragma unroll
    for (int g = 0; g < G_; g++) {
        use[g] = mg[g] > 0.5f;
        t[g]   = ig[g];
        cnt   += use[g] ? 1.f : 0.f;
    }
    float inv = valid ? (1.f / fmaxf(cnt, 1.f)) : 0.f;
    for (int c = tid; c < H_; c += blockDim.x) {
        float s = 0.f;
#pragma unroll
        for (int g = 0; g < G_; g++)
            if (use[g]) s += hb[(size_t)t[g] * H_ + c];
        xr[c] = s * inv;
    }
}

// ---------------- bf16x3 tensor-core GEMM ----------------
// C[M,N] = A[M,K] @ Wt[N,K]^T + bias (opt relu), fp32 in/out.
// Each operand split into bf16 hi + lo on the fly; 3 MMAs recover ~19-bit
// mantissa. 128x128 tile, BK=32, 8 warps (4m x 2n), 32x64 warp tile.
// smem word layout: stride 24 words/row; within a 16-k half, k-pair p is
// stored at word (p&3)*2 + (p>>2)  -> fragment reads become ld.shared.v2.u32.

__device__ __forceinline__ void mma16816(float* c, const unsigned* a, const unsigned* b) {
    asm volatile(
        "mma.sync.aligned.m16n8k16.row.col.f32.bf16.bf16.f32 "
        "{%0,%1,%2,%3}, {%4,%5,%6,%7}, {%8,%9}, {%0,%1,%2,%3};"
        : "+f"(c[0]), "+f"(c[1]), "+f"(c[2]), "+f"(c[3])
        : "r"(a[0]), "r"(a[1]), "r"(a[2]), "r"(a[3]), "r"(b[0]), "r"(b[1]));
}

__device__ __forceinline__ void store_split(unsigned* sh, unsigned* sl,
                                            int base, float4 v)
{
    __nv_bfloat162 h0 = __floats2bfloat162_rn(v.x, v.y);
    __nv_bfloat162 h1 = __floats2bfloat162_rn(v.z, v.w);
    float r0x = v.x - __bfloat162float(h0.x);
    float r0y = v.y - __bfloat162float(h0.y);
    float r1x = v.z - __bfloat162float(h1.x);
    float r1y = v.w - __bfloat162float(h1.y);
    __nv_bfloat162 l0 = __floats2bfloat162_rn(r0x, r0y);
    __nv_bfloat162 l1 = __floats2bfloat162_rn(r1x, r1y);
    sh[base]     = *reinterpret_cast<unsigned*>(&h0);
    sh[base + 2] = *reinterpret_cast<unsigned*>(&h1);
    sl[base]     = *reinterpret_cast<unsigned*>(&l0);
    sl[base + 2] = *reinterpret_cast<unsigned*>(&l1);
}

#define SSTR 24   // smem words per row (16 data words + 8 pad)

template <bool RELU>
__global__ void __launch_bounds__(256)
gemm_bf16x3_kernel(const float* __restrict__ A, const float* __restrict__ Wt,
                   const float* __restrict__ bias, float* __restrict__ C,
                   int M, int N, int K)
{
    __shared__ unsigned sAh[128 * SSTR], sAl[128 * SSTR];
    __shared__ unsigned sBh[128 * SSTR], sBl[128 * SSTR];

    const int tid = threadIdx.x;
    const int m0 = blockIdx.y * 128, n0 = blockIdx.x * 128;
    const int warp = tid >> 5, lane = tid & 31;
    const int g = lane >> 2, t = lane & 3;
    const int wm = warp & 3, wn = warp >> 2;   // 4 x 2 warp grid
    const int mbase = wm * 32, nbase = wn * 64;

    // gmem load mapping: 8 threads/row (float4 each), 32 rows per pass
    const int lrow = tid >> 3;
    const int lk4 = tid & 7;
    const int w0 = ((lk4 & 1) << 2) | ((lk4 >> 1) & 1) | ((lk4 >> 2) << 3);

    float acc[2][8][4];
#pragma unroll
    for (int mt = 0; mt < 2; mt++)
#pragma unroll
        for (int nt = 0; nt < 8; nt++)
#pragma unroll
            for (int i = 0; i < 4; i++) acc[mt][nt][i] = 0.f;

    float4 ra[4], rb4[4];
    // initial stage (k0 = 0)
#pragma unroll
    for (int p = 0; p < 4; p++) {
        int mrow = m0 + lrow + p * 32;
        ra[p] = (mrow < M) ? *(const float4*)&A[(size_t)mrow * K + lk4 * 4]
                           : make_float4(0.f, 0.f, 0.f, 0.f);
        rb4[p] = *(const float4*)&Wt[(size_t)(n0 + lrow + p * 32) * K + lk4 * 4];
    }

    for (int k0 = 0;; k0 += 32) {
        // commit staged tiles with hi/lo split
#pragma unroll
        for (int p = 0; p < 4; p++) {
            int base = (lrow + p * 32) * SSTR + w0;
            store_split(sAh, sAl, base, ra[p]);
            store_split(sBh, sBl, base, rb4[p]);
        }
        __syncthreads();

        bool more = (k0 + 32 < K);
        if (more) {
            int kb = k0 + 32 + lk4 * 4;
#pragma unroll
            for (int p = 0; p < 4; p++) {
                int mrow = m0 + lrow + p * 32;
                ra[p] = (mrow < M) ? *(const float4*)&A[(size_t)mrow * K + kb]
                                   : make_float4(0.f, 0.f, 0.f, 0.f);
                rb4[p] = *(const float4*)&Wt[(size_t)(n0 + lrow + p * 32) * K + kb];
            }
        }

#pragma unroll
        for (int ks = 0; ks < 2; ks++) {
            unsigned ah[2][4], al[2][4];
#pragma unroll
            for (int mt = 0; mt < 2; mt++) {
                int r0 = (mbase + mt * 16 + g) * SSTR + ks * 8 + t * 2;
                int r1 = r0 + 8 * SSTR;
                uint2 v;
                v = *(const uint2*)&sAh[r0]; ah[mt][0] = v.x; ah[mt][2] = v.y;
                v = *(const uint2*)&sAh[r1]; ah[mt][1] = v.x; ah[mt][3] = v.y;
                v = *(const uint2*)&sAl[r0]; al[mt][0] = v.x; al[mt][2] = v.y;
                v = *(const uint2*)&sAl[r1]; al[mt][1] = v.x; al[mt][3] = v.y;
            }
#pragma unroll
            for (int nt = 0; nt < 8; nt++) {
                int rbw = (nbase + nt * 8 + g) * SSTR + ks * 8 + t * 2;
                uint2 vh = *(const uint2*)&sBh[rbw];
                uint2 vl = *(const uint2*)&sBl[rbw];
                unsigned bh[2] = {vh.x, vh.y};
                unsigned bl[2] = {vl.x, vl.y};
#pragma unroll
                for (int mt = 0; mt < 2; mt++) {
                    mma16816(acc[mt][nt], ah[mt], bh);
                    mma16816(acc[mt][nt], al[mt], bh);
                    mma16816(acc[mt][nt], ah[mt], bl);
                }
            }
        }
        if (!more) break;
        __syncthreads();
    }

    // epilogue
#pragma unroll
    for (int nt = 0; nt < 8; nt++) {
        int col = n0 + nbase + nt * 8 + t * 2;
        float b0 = bias[col], b1 = bias[col + 1];
#pragma unroll
        for (int mt = 0; mt < 2; mt++) {
            int row0 = m0 + mbase + mt * 16 + g;
            float2 o0, o1;
            o0.x = acc[mt][nt][0] + b0;  o0.y = acc[mt][nt][1] + b1;
            o1.x = acc[mt][nt][2] + b0;  o1.y = acc[mt][nt][3] + b1;
            if (RELU) {
                o0.x = fmaxf(o0.x, 0.f); o0.y = fmaxf(o0.y, 0.f);
                o1.x = fmaxf(o1.x, 0.f); o1.y = fmaxf(o1.y, 0.f);
            }
            if (row0 < M)     *(float2*)&C[(size_t)row0 * N + col] = o0;
            if (row0 + 8 < M) *(float2*)&C[(size_t)(row0 + 8) * N + col] = o1;
        }
    }
}

// ---------------- attention as batched GEMMs (fp32) ----------------
__global__ void __launch_bounds__(256)
attn_score_kernel(const float* __restrict__ qkv,
                  const float* __restrict__ wvalid,
                  float* __restrict__ S)
{
    __shared__ float sA[16][72];
    __shared__ float sB[16][72];

    int bh = blockIdx.z, b = bh >> 2, h = bh & 3;
    int m0 = blockIdx.y * 64, n0 = blockIdx.x * 64;
    const float* Q  = qkv + (size_t)b * LW * (3 * H_) + h * HD_;
    const float* Kp = Q + H_;

    int tid = threadIdx.x;
    int kx4 = (tid & 3) * 4, rsel = tid >> 2;
    int tx = tid & 15, ty = tid >> 4;

    float acc[4][4];
#pragma unroll
    for (int i = 0; i < 4; i++)
#pragma unroll
        for (int j = 0; j < 4; j++) acc[i][j] = 0.f;

    for (int k0 = 0; k0 < HD_; k0 += 16) {
        int m = m0 + rsel, n = n0 + rsel;
        float4 a = make_float4(0.f, 0.f, 0.f, 0.f), bvv = a;
        if (m < LW) a   = *(const float4*)&Q [(size_t)m * (3 * H_) + k0 + kx4];
        if (n < LW) bvv = *(const float4*)&Kp[(size_t)n * (3 * H_) + k0 + kx4];
        sA[kx4 + 0][rsel] = a.x;  sA[kx4 + 1][rsel] = a.y;
        sA[kx4 + 2][rsel] = a.z;  sA[kx4 + 3][rsel] = a.w;
        sB[kx4 + 0][rsel] = bvv.x; sB[kx4 + 1][rsel] = bvv.y;
        sB[kx4 + 2][rsel] = bvv.z; sB[kx4 + 3][rsel] = bvv.w;
        __syncthreads();
#pragma unroll
        for (int k = 0; k < 16; k++) {
            float4 a4 = *(const float4*)&sA[k][ty * 4];
            float4 b4 = *(const float4*)&sB[k][tx * 4];
            float av[4] = {a4.x, a4.y, a4.z, a4.w};
            float bw[4] = {b4.x, b4.y, b4.z, b4.w};
#pragma unroll
            for (int i = 0; i < 4; i++)
#pragma unroll
                for (int j = 0; j < 4; j++) acc[i][j] += av[i] * bw[j];
        }
        __syncthreads();
    }

    const float scale = rsqrtf((float)HD_);
    float* Sb = S + (size_t)bh * LW * SLD;
#pragma unroll
    for (int j = 0; j < 4; j++) {
        int n = n0 + tx * 4 + j;
        if (n >= LW) continue;
        float mask = (n == 0 || wvalid[b * W_ + n - 1] > 0.5f) ? 0.f : -1e30f;
#pragma unroll
        for (int i = 0; i < 4; i++) {
            int m = m0 + ty * 4 + i;
            if (m < LW) Sb[(size_t)m * SLD + n] = acc[i][j] * scale + mask;
        }
    }
}

__global__ void __launch_bounds__(256)
attn_softmax_kernel(float* __restrict__ S)
{
    int row = blockIdx.x * 8 + (threadIdx.x >> 5);
    if (row >= B_ * NH_ * LW) return;
    int lane = threadIdx.x & 31;
    float* p = S + (size_t)row * SLD;

    float mx = -1e30f;
    for (int k = lane; k < LW; k += 32) mx = fmaxf(mx, p[k]);
#pragma unroll
    for (int o = 16; o > 0; o >>= 1) mx = fmaxf(mx, __shfl_xor_sync(0xffffffffu, mx, o));
    float sum = 0.f;
    float e0 = 0.f, e1 = 0.f, e2 = 0.f, e3 = 0.f, e4 = 0.f;
    {
        int k = lane;
        e0 = __expf(p[k] - mx); sum += e0; k += 32;
        e1 = __expf(p[k] - mx); sum += e1; k += 32;
        e2 = __expf(p[k] - mx); sum += e2; k += 32;
        e3 = __expf(p[k] - mx); sum += e3; k += 32;
        if (k < LW) { e4 = __expf(p[k] - mx); sum += e4; }
    }
#pragma unroll
    for (int o = 16; o > 0; o >>= 1) sum += __shfl_xor_sync(0xffffffffu, sum, o);
    float inv = 1.f / sum;
    {
        int k = lane;
        p[k] = e0 * inv; k += 32;
        p[k] = e1 * inv; k += 32;
        p[k] = e2 * inv; k += 32;
        p[k] = e3 * inv; k += 32;
        if (k < SLD) p[k] = (k < LW) ? e4 * inv : 0.f;
    }
}

__global__ void __launch_bounds__(256)
attn_av_kernel(const float* __restrict__ S,
               const float* __restrict__ qkv,
               float* __restrict__ ctx)
{
    __shared__ float sA[16][72];
    __shared__ float sB[16][72];
    int bh = blockIdx.z, b = bh >> 2, h = bh & 3;
    int m0 = blockIdx.y * 64, n0 = blockIdx.x * 64;
    const float* P = S + (size_t)bh * LW * SLD;
    const float* V = qkv + (size_t)b * LW * (3 * H_) + 2 * H_ + h * HD_;

    int tid = threadIdx.x;
    int kx4 = (tid & 3) * 4, rsel = tid >> 2;
    int ksel = tid >> 4, nx4 = (tid & 15) * 4;
    int tx = tid & 15, ty = tid >> 4;

    float acc[4][4];
#pragma unroll
    for (int i = 0; i < 4; i++)
#pragma unroll
        for (int j = 0; j < 4; j++) acc[i][j] = 0.f;

    for (int k0 = 0; k0 < LW; k0 += 16) {
        int m = m0 + rsel;
        float4 a = make_float4(0.f, 0.f, 0.f, 0.f);
        if (m < LW && k0 + kx4 <= SLD - 4)
            a = *(const float4*)&P[(size_t)m * SLD + k0 + kx4];
        float4 bvv = make_float4(0.f, 0.f, 0.f, 0.f);
        int kr = k0 + ksel;
        if (kr < LW)
            bvv = *(const float4*)&V[(size_t)kr * (3 * H_) + n0 + nx4];
        sA[kx4 + 0][rsel] = a.x;  sA[kx4 + 1][rsel] = a.y;
        sA[kx4 + 2][rsel] = a.z;  sA[kx4 + 3][rsel] = a.w;
        *(float4*)&sB[ksel][nx4] = bvv;
        __syncthreads();
#pragma unroll
        for (int k = 0; k < 16; k++) {
            float4 a4 = *(const float4*)&sA[k][ty * 4];
            float4 b4 = *(const float4*)&sB[k][tx * 4];
            float av[4] = {a4.x, a4.y, a4.z, a4.w};
            float bw[4] = {b4.x, b4.y, b4.z, b4.w};
#pragma unroll
            for (int i = 0; i < 4; i++)
#pragma unroll
                for (int j = 0; j < 4; j++) acc[i][j] += av[i] * bw[j];
        }
        __syncthreads();
    }

#pragma unroll
    for (int i = 0; i < 4; i++) {
        int m = m0 + ty * 4 + i;
        if (m >= LW) continue;
        float4 o;
        o.x = acc[i][0]; o.y = acc[i][1]; o.z = acc[i][2]; o.w = acc[i][3];
        *(float4*)&ctx[(size_t)(b * LW + m) * H_ + h * HD_ + n0 + tx * 4] = o;
    }
}

// ---------------- fused residual-add + layernorm (in-place into x) ----------------
__global__ void __launch_bounds__(256)
add_ln_kernel(float* __restrict__ x, const float* __restrict__ y,
              const float* __restrict__ s, const float* __restrict__ bb)
{
    __shared__ float red[32];
    int row = blockIdx.x, tid = threadIdx.x;
    float* xr = x + (size_t)row * H_;
    const float* yr = y + (size_t)row * H_;

    float h[3];
    float sum = 0.f;
#pragma unroll
    for (int i = 0; i < 3; i++) {
        int c = tid + i * 256;
        h[i] = xr[c] + yr[c];
        sum += h[i];
    }
    int lane = tid & 31, w = tid >> 5;
#pragma unroll
    for (int o = 16; o > 0; o >>= 1) sum += __shfl_xor_sync(0xffffffffu, sum, o);
    if (lane == 0) red[w] = sum;
    __syncthreads();
    if (w == 0) {
        float v = (lane < 8) ? red[lane] : 0.f;
#pragma unroll
        for (int o = 4; o > 0; o >>= 1) v += __shfl_xor_sync(0xffu, v, o);
        if (lane == 0) red[0] = v;
    }
    __syncthreads();
    float mean = red[0] * (1.f / H_);
    __syncthreads();

    float vs = 0.f;
#pragma unroll
    for (int i = 0; i < 3; i++) {
        float d = h[i] - mean;
        vs += d * d;
    }
#pragma unroll
    for (int o = 16; o > 0; o >>= 1) vs += __shfl_xor_sync(0xffffffffu, vs, o);
    if (lane == 0) red[w] = vs;
    __syncthreads();
    if (w == 0) {
        float v = (lane < 8) ? red[lane] : 0.f;
#pragma unroll
        for (int o = 4; o > 0; o >>= 1) v += __shfl_xor_sync(0xffu, v, o);
        if (lane == 0) red[0] = v;
    }
    __syncthreads();
    float var = red[0] * (1.f / H_);
    float rstd = rsqrtf(var + EPS_);

#pragma unroll
    for (int i = 0; i < 3; i++) {
        int c = tid + i * 256;
        xr[c] = (h[i] - mean) * rstd * s[c] + bb[c];
    }
}

// ---------------- classifier head + pooled copy ----------------
__global__ void __launch_bounds__(256)
cls_kernel(const float* __restrict__ x, const float* __restrict__ cw,
           const float* __restrict__ cb, float* __restrict__ out)
{
    int b = blockIdx.x, tid = threadIdx.x;
    const float* p = x + (size_t)b * LW * H_;
    float* pooled = out + NLAB_ * B_ + (size_t)b * H_;
    for (int c = tid; c < H_; c += 256) pooled[c] = p[c];

    int warp = tid >> 5, lane = tid & 31;
    if (warp < NLAB_) {
        float s = 0.f;
        for (int c = lane; c < H_; c += 32) s += p[c] * cw[(size_t)warp * H_ + c];
#pragma unroll
        for (int o = 16; o > 0; o >>= 1) s += __shfl_xor_sync(0xffffffffu, s, o);
        if (lane == 0) out[b * NLAB_ + warp] = s + cb[warp];
    }
}

// ---------------- launcher ----------------
extern "C" void kernel_launch(void* const* d_in, const int* in_sizes, int n_in,
                              void* d_out, int out_size)
{
    const float* hidden = (const float*)d_in[0];
    const int*   widx   = (const int*)d_in[1];
    const void*  gmask  = (const void*)d_in[2];
    const void*  wvalid = (const void*)d_in[3];
    const float* qkv_w = (const float*)d_in[4];
    const float* qkv_b = (const float*)d_in[5];
    const float* out_w = (const float*)d_in[6];
    const float* out_b = (const float*)d_in[7];
    const float* ff1_w = (const float*)d_in[8];
    const float* ff1_b = (const float*)d_in[9];
    const float* ff2_w = (const float*)d_in[10];
    const float* ff2_b = (const float*)d_in[11];
    const float* ln1_s = (const float*)d_in[12];
    const float* ln1_b = (const float*)d_in[13];
    const float* ln2_s = (const float*)d_in[14];
    const float* ln2_b = (const float*)d_in[15];
    const float* cls_w = (const float*)d_in[16];
    const float* cls_b = (const float*)d_in[17];
    float* out = (float*)d_out;

    float *px, *pqkv, *ptmp, *pctx, *pgm, *pwv;
    cudaGetSymbolAddress((void**)&px,   g_x);
    cudaGetSymbolAddress((void**)&pqkv, g_qkv);
    cudaGetSymbolAddress((void**)&ptmp, g_tmp);
    cudaGetSymbolAddress((void**)&pctx, g_ctx);
    cudaGetSymbolAddress((void**)&pgm,  g_gm);
    cudaGetSymbolAddress((void**)&pwv,  g_wv);

    norm_mask_kernel<<<1, 256>>>(gmask, wvalid, pgm, pwv);
    build_x_kernel<<<MT, 256>>>(hidden, widx, pgm, pwv, px);

    const int MTILES = (MT + 127) / 128;   // 33
    const int SROWS = B_ * NH_ * LW;       // 16512
    for (int l = 0; l < NL_; l++) {
        // qkv = x @ qkv_w^T + b     (M=4128, N=2304, K=768)
        {
            dim3 grid(3 * H_ / 128, MTILES);
            gemm_bf16x3_kernel<false><<<grid, 256>>>(px, qkv_w + (size_t)l * 3 * H_ * H_,
                                                     qkv_b + (size_t)l * 3 * H_, pqkv,
                                                     MT, 3 * H_, H_);
        }
        // attention: scores -> softmax -> AV
        {
            dim3 grid(3, 3, B_ * NH_);
            attn_score_kernel<<<grid, 256>>>(pqkv, pwv, ptmp);
            attn_softmax_kernel<<<(SROWS + 7) / 8, 256>>>(ptmp);
            dim3 gav(HD_ / 64, 3, B_ * NH_);
            attn_av_kernel<<<gav, 256>>>(ptmp, pqkv, pctx);
        }
        // attn_out = ctx @ out_w^T + b  (N=768, K=768) -> tmp
        {
            dim3 grid(H_ / 128, MTILES);
            gemm_bf16x3_kernel<false><<<grid, 256>>>(pctx, out_w + (size_t)l * H_ * H_,
                                                     out_b + (size_t)l * H_, ptmp,
                                                     MT, H_, H_);
        }
        // x = LN1(x + attn_out)
        add_ln_kernel<<<MT, 256>>>(px, ptmp, ln1_s + (size_t)l * H_, ln1_b + (size_t)l * H_);
        // h1 = relu(x @ ff1_w^T + b)  (N=2048, K=768) -> tmp
        {
            dim3 grid(FF_ / 128, MTILES);
            gemm_bf16x3_kernel<true><<<grid, 256>>>(px, ff1_w + (size_t)l * FF_ * H_,
                                                    ff1_b + (size_t)l * FF_, ptmp,
                                                    MT, FF_, H_);
        }
        // ff_out = h1 @ ff2_w^T + b   (N=768, K=2048) -> ctx
        {
            dim3 grid(H_ / 128, MTILES);
            gemm_bf16x3_kernel<false><<<grid, 256>>>(ptmp, ff2_w + (size_t)l * H_ * FF_,
                                                     ff2_b + (size_t)l * H_, pctx,
                                                     MT, H_, FF_);
        }
        // x = LN2(x + ff_out)
        add_ln_kernel<<<MT, 256>>>(px, pctx, ln2_s + (size_t)l * H_, ln2_b + (size_t)l * H_);
    }

    cls_kernel<<<B_, 256>>>(px, cls_w, cls_b, out);
}